// round 5
// baseline (speedup 1.0000x reference)
#include <cuda_runtime.h>
#include <cstdint>

#define CZ  128
#define HD  64
#define P   64      // pixels per CTA
#define NT  512
#define NW  16      // warps
#define XST 132     // stride for 128-wide [row][k] tiles (even!)
#define QST 68      // stride for 64-wide [row][c] tiles (mult of 4)

static __device__ __forceinline__ float tf32r(float x) {
    float y; asm("cvt.rna.tf32.f32 %0, %1;" : "=f"(y) : "f"(x)); return y;
}
// interleaved-k position: pairs (k, k+4) become adjacent floats
static __device__ __forceinline__ int kperm(int k) {
    return (k & ~7) | ((k & 3) << 1) | ((k >> 2) & 1);
}

static __device__ __forceinline__ void mma8(float* d,
    float a0, float a1, float a2, float a3, float b0, float b1)
{
    asm volatile("mma.sync.aligned.m16n8k8.row.col.f32.tf32.tf32.f32 "
        "{%0,%1,%2,%3}, {%4,%5,%6,%7}, {%8,%9}, {%0,%1,%2,%3};"
        : "+f"(d[0]), "+f"(d[1]), "+f"(d[2]), "+f"(d[3])
        : "r"(__float_as_uint(a0)), "r"(__float_as_uint(a1)),
          "r"(__float_as_uint(a2)), "r"(__float_as_uint(a3)),
          "r"(__float_as_uint(b0)), "r"(__float_as_uint(b1)));
}

// Warp computes 16 rows (mt) x 32 cols (nq), K = 8*KT.
// A: [row][kperm] stride ast (even); B: wt[n][kperm] stride XST.
static __device__ __forceinline__ void gemm_warp(
    float acc[4][4], const float* A, int ast, const float* wt,
    int mt, int nq, int gid, int tig, int KT)
{
    const float2* a0p = (const float2*)(A + (mt * 16 + gid) * ast) + tig;
    const float2* a1p = (const float2*)(A + (mt * 16 + gid + 8) * ast) + tig;
    const float2* bp  = (const float2*)(wt + (nq * 32 + gid) * XST) + tig;
    #pragma unroll 4
    for (int kt = 0; kt < KT; kt++) {
        float2 A0 = a0p[kt * 4];     // (a0, a2) = k0+tig, k0+tig+4
        float2 A1 = a1p[kt * 4];     // (a1, a3)
        #pragma unroll
        for (int nt = 0; nt < 4; nt++) {
            float2 B = bp[nt * 8 * (XST / 2) + kt * 4];
            mma8(acc[nt], A0.x, A1.x, A0.y, A1.y, B.x, B.y);
        }
    }
}

// LayerNorm 64 rows x 128 cols -> tf32 into [row][kperm] stride XST.
static __device__ __forceinline__ void ln64(
    const float* __restrict__ src, long base, int R, float* dst,
    float4 g4, float4 b4, int wid, int lane)
{
    const int c4  = lane * 4;
    const int rot = lane >> 3;                       // conflict-free store rotation
    const int dof = (c4 & ~7) + ((c4 >> 2) & 1);     // interleaved base for this lane
    #pragma unroll
    for (int r = wid; r < P; r += NW) {
        long row = base + r;
        float4 x = make_float4(0.f, 0.f, 0.f, 0.f);
        if (row < R) x = *(const float4*)(src + row * (long)CZ + c4);
        float s = x.x + x.y + x.z + x.w;
        float q = fmaf(x.x, x.x, fmaf(x.y, x.y, fmaf(x.z, x.z, x.w * x.w)));
        #pragma unroll
        for (int o = 16; o; o >>= 1) {
            s += __shfl_xor_sync(0xffffffffu, s, o);
            q += __shfl_xor_sync(0xffffffffu, q, o);
        }
        float m  = s * (1.f / CZ);
        float v  = fmaxf(q * (1.f / CZ) - m * m, 0.f);
        float ri = rsqrtf(v + 1e-5f);
        float yv[4];
        yv[0] = tf32r((x.x - m) * ri * g4.x + b4.x);
        yv[1] = tf32r((x.y - m) * ri * g4.y + b4.y);
        yv[2] = tf32r((x.z - m) * ri * g4.z + b4.z);
        yv[3] = tf32r((x.w - m) * ri * g4.w + b4.w);
        float* drow = dst + r * XST + dof;
        #pragma unroll
        for (int s4 = 0; s4 < 4; s4++) {
            int j = (s4 + rot) & 3;
            drow[j * 2] = yv[j];
        }
    }
}

// Stage two k-major [128][64] weights into wt[n][kperm].
static __device__ __forceinline__ void stageW2(
    float* wt, const float* __restrict__ W1, const float* __restrict__ W2, int tid)
{
    #pragma unroll 1
    for (int i = tid; i < 4096; i += NT) {
        const int m  = i >> 11;
        const int k  = (i >> 4) & 127;
        const int ng = i & 15;
        const float* Ws = m ? W2 : W1;
        float4 w = *(const float4*)(Ws + k * HD + ng * 4);
        const int n  = m * 64 + ng * 4;
        const int pk = kperm(k);
        wt[(n + 0) * XST + pk] = tf32r(w.x);
        wt[(n + 1) * XST + pk] = tf32r(w.y);
        wt[(n + 2) * XST + pk] = tf32r(w.z);
        wt[(n + 3) * XST + pk] = tf32r(w.w);
    }
}

__global__ void __launch_bounds__(NT, 1)
tpa_mma3(const float* __restrict__ tmpl, const float* __restrict__ pair,
         const float* __restrict__ lpg, const float* __restrict__ lpb,
         const float* __restrict__ ltg, const float* __restrict__ ltb,
         const float* __restrict__ Wq,  const float* __restrict__ Wk,
         const float* __restrict__ Wv,  const float* __restrict__ Wg,
         const float* __restrict__ bg,  const float* __restrict__ Wo,
         const float* __restrict__ bo,  float* __restrict__ out,
         int R, int T)
{
    extern __shared__ float smf[];
    float* xs0 = smf;                 // 64 x XST : LN buffer A (interleaved k)
    float* xs1 = xs0 + P * XST;       // 64 x XST : LN buffer B
    float* wt  = xs1 + P * XST;       // 128 x XST: weights [n][kperm]
    float* qs  = wt + 128 * XST;      // 64 x QST : Q (plain cols)
    float* ks  = qs + P * QST;        // 64 x QST : K_t (plain) / vals (interleaved)
    float* rs  = ks + P * QST;        // 256 : rescale / 1/l
    float* ws  = rs + 256;            // 256 : new weight
    float* bgs = ws + 256;            // 64
    float* bos = bgs + HD;            // 128

    const int tid  = threadIdx.x;
    const int lane = tid & 31;
    const int wid  = tid >> 5;
    const int mt   = wid & 3;         // m-tile (16 rows)
    const int nq   = wid >> 2;        // n quarter (32 cols)
    const int gid  = lane >> 2;
    const int tig  = lane & 3;
    const long base = (long)blockIdx.x * P;

    if (tid < HD)  bgs[tid] = bg[tid];
    else if (tid >= 64 && tid < 64 + CZ) bos[tid - 64] = bo[tid - 64];

    const int c4 = lane * 4;
    const float4 gp = *(const float4*)(lpg + c4), bp = *(const float4*)(lpb + c4);
    const float4 gt = *(const float4*)(ltg + c4), bt = *(const float4*)(ltb + c4);

    // ---------------- Phase A: LN(pair)->xs0, Wq|Wg, QG GEMM ----------------
    ln64(pair, base, R, xs0, gp, bp, wid, lane);
    stageW2(wt, Wq, Wg, tid);
    __syncthreads();

    float g[4][4];                    // only meaningful on nq>=2 warps
    {
        float qga[4][4] = {};
        gemm_warp(qga, xs0, XST, wt, mt, nq, gid, tig, 16);
        if (nq < 2) {                 // Q -> smem (plain layout)
            const int p0 = mt * 16 + gid, p1 = p0 + 8;
            #pragma unroll
            for (int nt = 0; nt < 4; nt++) {
                const int c = nq * 32 + nt * 8 + tig * 2;
                qs[p0 * QST + c]     = qga[nt][0];
                qs[p0 * QST + c + 1] = qga[nt][1];
                qs[p1 * QST + c]     = qga[nt][2];
                qs[p1 * QST + c + 1] = qga[nt][3];
            }
        } else {                      // G kept in fragments (sigmoid)
            #pragma unroll
            for (int nt = 0; nt < 4; nt++) {
                const int c = (nq - 2) * 32 + nt * 8 + tig * 2;
                g[nt][0] = 1.f / (1.f + __expf(-(qga[nt][0] + bgs[c])));
                g[nt][1] = 1.f / (1.f + __expf(-(qga[nt][1] + bgs[c + 1])));
                g[nt][2] = 1.f / (1.f + __expf(-(qga[nt][2] + bgs[c])));
                g[nt][3] = 1.f / (1.f + __expf(-(qga[nt][3] + bgs[c + 1])));
            }
        }
    }
    ln64(tmpl, base, R, xs1, gt, bt, wid, lane);   // LN(t=0) -> xs1
    __syncthreads();

    // Q into registers of score threads (tid<256), Wk|Wv staged
    float qreg[16];
    float m_run = __int_as_float(0xff800000), l_run = 0.f;
    if (tid < 256) {
        const int sp = tid >> 2, sh = tid & 3;
        const float4* qp = (const float4*)(qs + sp * QST + sh * 16);
        #pragma unroll
        for (int qd = 0; qd < 4; qd++) {
            float4 v = qp[qd];
            qreg[qd * 4 + 0] = v.x; qreg[qd * 4 + 1] = v.y;
            qreg[qd * 4 + 2] = v.z; qreg[qd * 4 + 3] = v.w;
        }
    }
    stageW2(wt, Wk, Wv, tid);
    float vAcc[4][4] = {};
    __syncthreads();

    // ---------------- template loop (2 syncs per t) ----------------
    #pragma unroll 1
    for (int t = 0; t < T; t++) {
        const float* xsc = (t & 1) ? xs0 : xs1;
        float kv[4][4] = {};
        gemm_warp(kv, xsc, XST, wt, mt, nq, gid, tig, 16);
        if (nq < 2) {                 // K -> smem (plain layout)
            const int p0 = mt * 16 + gid, p1 = p0 + 8;
            #pragma unroll
            for (int nt = 0; nt < 4; nt++) {
                const int c = nq * 32 + nt * 8 + tig * 2;
                ks[p0 * QST + c]     = kv[nt][0];
                ks[p0 * QST + c + 1] = kv[nt][1];
                ks[p1 * QST + c]     = kv[nt][2];
                ks[p1 * QST + c + 1] = kv[nt][3];
            }
        }
        __syncthreads();              // S1: ks ready; prev V-acc done (rs/ws reusable)

        if (tid < 256) {              // scores + online softmax, thread owns (p,h)
            const int sp = tid >> 2, sh = tid & 3;
            const float4* kp = (const float4*)(ks + sp * QST + sh * 16);
            float sdot = 0.f;
            #pragma unroll
            for (int qd = 0; qd < 4; qd++) {
                float4 kq = kp[qd];
                sdot = fmaf(qreg[qd * 4 + 0], kq.x, sdot);
                sdot = fmaf(qreg[qd * 4 + 1], kq.y, sdot);
                sdot = fmaf(qreg[qd * 4 + 2], kq.z, sdot);
                sdot = fmaf(qreg[qd * 4 + 3], kq.w, sdot);
            }
            sdot *= 0.25f;            // 1/sqrt(D=16)
            float mn = fmaxf(m_run, sdot);
            float rr = __expf(m_run - mn);
            float ww = __expf(sdot - mn);
            l_run = l_run * rr + ww;
            m_run = mn;
            rs[tid] = rr;
            ws[tid] = ww;
        }
        if (t + 1 < T)
            ln64(tmpl + (long)(t + 1) * R * CZ, base, R,
                 (t & 1) ? xs1 : xs0, gt, bt, wid, lane);
        __syncthreads();              // S2: rs/ws + xs(t+1) ready

        if (nq >= 2) {                // V online accumulate (overlaps next GEMM)
            const int p0 = mt * 16 + gid, p1 = p0 + 8;
            const int hb = (nq - 2) * 2;
            #pragma unroll
            for (int nt = 0; nt < 4; nt++) {
                const int h = hb + (nt >> 1);
                float rr0 = rs[p0 * 4 + h], ww0 = ws[p0 * 4 + h];
                float rr1 = rs[p1 * 4 + h], ww1 = ws[p1 * 4 + h];
                vAcc[nt][0] = fmaf(vAcc[nt][0], rr0, ww0 * kv[nt][0]);
                vAcc[nt][1] = fmaf(vAcc[nt][1], rr0, ww0 * kv[nt][1]);
                vAcc[nt][2] = fmaf(vAcc[nt][2], rr1, ww1 * kv[nt][2]);
                vAcc[nt][3] = fmaf(vAcc[nt][3], rr1, ww1 * kv[nt][3]);
            }
        }
        // no sync: V-acc completes before S1 of next iter guards rs/ws overwrite
    }
    __syncthreads();                  // V-acc done everywhere; rs reusable

    // ---------------- Phase C: finalize, Wo, O GEMM ----------------
    if (tid < 256) rs[tid] = 1.f / l_run;       // linv per (p,h)
    {   // stage Wo[k=64][n=128] -> wt[n][kperm]
        #pragma unroll 1
        for (int i = tid; i < 2048; i += NT) {
            const int k = i >> 5, ng = i & 31;
            float4 w = *(const float4*)(Wo + k * CZ + ng * 4);
            const int n  = ng * 4;
            const int pk = kperm(k);
            wt[(n + 0) * XST + pk] = tf32r(w.x);
            wt[(n + 1) * XST + pk] = tf32r(w.y);
            wt[(n + 2) * XST + pk] = tf32r(w.z);
            wt[(n + 3) * XST + pk] = tf32r(w.w);
        }
    }
    __syncthreads();

    if (nq >= 2) {                    // vals = vAcc * G * linv -> ks (interleaved)
        const int p0 = mt * 16 + gid, p1 = p0 + 8;
        const int hb = (nq - 2) * 2;
        #pragma unroll
        for (int nt = 0; nt < 4; nt++) {
            const int c  = (nq - 2) * 32 + nt * 8 + tig * 2;
            const int pc = kperm(c);  // kperm(c+1) == pc+2 for these c
            const int h  = hb + (nt >> 1);
            float li0 = rs[p0 * 4 + h], li1 = rs[p1 * 4 + h];
            ks[p0 * QST + pc]     = tf32r(vAcc[nt][0] * g[nt][0] * li0);
            ks[p0 * QST + pc + 2] = tf32r(vAcc[nt][1] * g[nt][1] * li0);
            ks[p1 * QST + pc]     = tf32r(vAcc[nt][2] * g[nt][2] * li1);
            ks[p1 * QST + pc + 2] = tf32r(vAcc[nt][3] * g[nt][3] * li1);
        }
    }
    __syncthreads();

    {
        float oc[4][4] = {};
        gemm_warp(oc, ks, QST, wt, mt, nq, gid, tig, 8);
        const long r0 = base + mt * 16 + gid, r1 = r0 + 8;
        #pragma unroll
        for (int nt = 0; nt < 4; nt++) {
            const int c = nq * 32 + nt * 8 + tig * 2;
            if (r0 < R) {
                float2 v = make_float2(oc[nt][0] + bos[c], oc[nt][1] + bos[c + 1]);
                *(float2*)(out + r0 * (long)CZ + c) = v;
            }
            if (r1 < R) {
                float2 v = make_float2(oc[nt][2] + bos[c], oc[nt][3] + bos[c + 1]);
                *(float2*)(out + r1 * (long)CZ + c) = v;
            }
        }
    }
}

extern "C" void kernel_launch(void* const* d_in, const int* in_sizes, int n_in,
                              void* d_out, int out_size)
{
    const float* tmpl = (const float*)d_in[0];
    const float* pair = (const float*)d_in[1];
    const float* lpg  = (const float*)d_in[2];
    const float* lpb  = (const float*)d_in[3];
    const float* ltg  = (const float*)d_in[4];
    const float* ltb  = (const float*)d_in[5];
    const float* Wq   = (const float*)d_in[6];
    const float* Wk   = (const float*)d_in[7];
    const float* Wv   = (const float*)d_in[8];
    const float* Wg   = (const float*)d_in[9];
    const float* bg   = (const float*)d_in[10];
    const float* Wo   = (const float*)d_in[11];
    const float* bo   = (const float*)d_in[12];
    float* out = (float*)d_out;

    const int R = in_sizes[1] / CZ;           // b*n*n pixels
    const int T = in_sizes[0] / in_sizes[1];  // templates

    const size_t smem = (size_t)(2 * P * XST + 128 * XST + 2 * P * QST
                                 + 2 * 256 + HD + CZ) * sizeof(float);
    cudaFuncSetAttribute(tpa_mma3, cudaFuncAttributeMaxDynamicSharedMemorySize, (int)smem);

    const int grid = (R + P - 1) / P;
    tpa_mma3<<<grid, NT, smem>>>(tmpl, pair, lpg, lpb, ltg, ltb,
                                 Wq, Wk, Wv, Wg, bg, Wo, bo, out, R, T);
}

// round 6
// speedup vs baseline: 1.0365x; 1.0365x over previous
#include <cuda_runtime.h>
#include <cstdint>

#define CZ  128
#define HD  64
#define P   64      // pixels per CTA
#define NT  512
#define NW  16
#define XST 136     // 128-wide rows; XST/2=68, 68 mod 16 = 4 -> conflict-free LDS.64
#define QST 72      // 64-wide rows;  QST/2=36, 36 mod 16 = 4

static __device__ __forceinline__ float tf32r(float x) {
    float y; asm("cvt.rna.tf32.f32 %0, %1;" : "=f"(y) : "f"(x)); return y;
}
// interleaved-k position: pairs (k, k+4) adjacent
static __device__ __forceinline__ int kperm(int k) {
    return (k & ~7) | ((k & 3) << 1) | ((k >> 2) & 1);
}

static __device__ __forceinline__ void mma8(float* d,
    float a0, float a1, float a2, float a3, float b0, float b1)
{
    asm volatile("mma.sync.aligned.m16n8k8.row.col.f32.tf32.tf32.f32 "
        "{%0,%1,%2,%3}, {%4,%5,%6,%7}, {%8,%9}, {%0,%1,%2,%3};"
        : "+f"(d[0]), "+f"(d[1]), "+f"(d[2]), "+f"(d[3])
        : "r"(__float_as_uint(a0)), "r"(__float_as_uint(a1)),
          "r"(__float_as_uint(a2)), "r"(__float_as_uint(a3)),
          "r"(__float_as_uint(b0)), "r"(__float_as_uint(b1)));
}

// Warp: 16 rows (mt) x 32 cols (nq), K = 8*KT. A [row][kperm] stride ast, B wt[n][kperm].
static __device__ __forceinline__ void gemm_warp(
    float acc[4][4], const float* A, int ast, const float* wt,
    int mt, int nq, int gid, int tig, int KT)
{
    const float2* a0p = (const float2*)(A + (mt * 16 + gid) * ast) + tig;
    const float2* a1p = (const float2*)(A + (mt * 16 + gid + 8) * ast) + tig;
    const float2* bp  = (const float2*)(wt + (nq * 32 + gid) * XST) + tig;
    #pragma unroll 4
    for (int kt = 0; kt < KT; kt++) {
        float2 A0 = a0p[kt * 4];     // (k0+tig, k0+tig+4)
        float2 A1 = a1p[kt * 4];
        #pragma unroll
        for (int nt = 0; nt < 4; nt++) {
            float2 B = bp[nt * 8 * (XST / 2) + kt * 4];
            mma8(acc[nt], A0.x, A1.x, A0.y, A1.y, B.x, B.y);
        }
    }
}

// Two-template KV GEMM: B fragments loaded once, reused for both templates.
static __device__ __forceinline__ void gemm_pair(
    float kv0[4][4], float kv1[4][4],
    const float* x0, const float* x1, const float* wt,
    int mt, int nq, int gid, int tig, bool doT1)
{
    const float2* a00 = (const float2*)(x0 + (mt * 16 + gid) * XST) + tig;
    const float2* a01 = (const float2*)(x0 + (mt * 16 + gid + 8) * XST) + tig;
    const float2* a10 = (const float2*)(x1 + (mt * 16 + gid) * XST) + tig;
    const float2* a11 = (const float2*)(x1 + (mt * 16 + gid + 8) * XST) + tig;
    const float2* bp  = (const float2*)(wt + (nq * 32 + gid) * XST) + tig;
    #pragma unroll 2
    for (int kt = 0; kt < 16; kt++) {
        float2 A00 = a00[kt * 4], A01 = a01[kt * 4];
        float2 A10, A11;
        if (doT1) { A10 = a10[kt * 4]; A11 = a11[kt * 4]; }
        #pragma unroll
        for (int nt = 0; nt < 4; nt++) {
            float2 B = bp[nt * 8 * (XST / 2) + kt * 4];
            mma8(kv0[nt], A00.x, A01.x, A00.y, A01.y, B.x, B.y);
            if (doT1) mma8(kv1[nt], A10.x, A11.x, A10.y, A11.y, B.x, B.y);
        }
    }
}

// LayerNorm 64 rows x 128 cols -> tf32 into [row][kperm] stride XST.
static __device__ __forceinline__ void ln64(
    const float* __restrict__ src, long base, int R, float* dst,
    float4 g4, float4 b4, int wid, int lane)
{
    const int c4  = lane * 4;
    const int rot = lane >> 3;                      // conflict-free store rotation
    const int dof = 8 * (lane >> 1) + (lane & 1);   // kperm base for this lane
    #pragma unroll
    for (int r = wid; r < P; r += NW) {
        long row = base + r;
        float4 x = make_float4(0.f, 0.f, 0.f, 0.f);
        if (row < R) x = *(const float4*)(src + row * (long)CZ + c4);
        float s = x.x + x.y + x.z + x.w;
        float q = fmaf(x.x, x.x, fmaf(x.y, x.y, fmaf(x.z, x.z, x.w * x.w)));
        #pragma unroll
        for (int o = 16; o; o >>= 1) {
            s += __shfl_xor_sync(0xffffffffu, s, o);
            q += __shfl_xor_sync(0xffffffffu, q, o);
        }
        float m  = s * (1.f / CZ);
        float v  = fmaxf(q * (1.f / CZ) - m * m, 0.f);
        float ri = rsqrtf(v + 1e-5f);
        float yv[4];
        yv[0] = tf32r((x.x - m) * ri * g4.x + b4.x);
        yv[1] = tf32r((x.y - m) * ri * g4.y + b4.y);
        yv[2] = tf32r((x.z - m) * ri * g4.z + b4.z);
        yv[3] = tf32r((x.w - m) * ri * g4.w + b4.w);
        float* drow = dst + r * XST + dof;
        #pragma unroll
        for (int s4 = 0; s4 < 4; s4++) {
            int j = (s4 + rot) & 3;
            drow[j * 2] = yv[j];
        }
    }
}

// Stage two k-major [128][64] weights into wt[n][kperm] (n<64: W1, else W2).
static __device__ __forceinline__ void stageW2(
    float* wt, const float* __restrict__ W1, const float* __restrict__ W2, int tid)
{
    #pragma unroll 1
    for (int i = tid; i < 4096; i += NT) {
        const int m  = i >> 11;
        const int k  = (i >> 4) & 127;
        const int ng = i & 15;
        const float* Ws = m ? W2 : W1;
        float4 w = *(const float4*)(Ws + k * HD + ng * 4);
        const int n  = m * 64 + ng * 4;
        const int pk = kperm(k);
        wt[(n + 0) * XST + pk] = tf32r(w.x);
        wt[(n + 1) * XST + pk] = tf32r(w.y);
        wt[(n + 2) * XST + pk] = tf32r(w.z);
        wt[(n + 3) * XST + pk] = tf32r(w.w);
    }
}

__global__ void __launch_bounds__(NT, 1)
tpa_mma4(const float* __restrict__ tmpl, const float* __restrict__ pair,
         const float* __restrict__ lpg, const float* __restrict__ lpb,
         const float* __restrict__ ltg, const float* __restrict__ ltb,
         const float* __restrict__ Wq,  const float* __restrict__ Wk,
         const float* __restrict__ Wv,  const float* __restrict__ Wg,
         const float* __restrict__ bg,  const float* __restrict__ Wo,
         const float* __restrict__ bo,  float* __restrict__ out,
         int R, int T)
{
    extern __shared__ float smf[];
    float* xs0 = smf;                 // 64 x XST : LN'd template t_even (or pair)
    float* xs1 = xs0 + P * XST;       // 64 x XST : LN'd template t_odd
    float* wt  = xs1 + P * XST;       // 128 x XST: weights [n][kperm]
    float* qs  = wt + 128 * XST;      // 64 x QST : Q (plain cols)
    float* ks  = qs + P * QST;        // 128 x QST: K (both templates) / vals (64 rows)
    float* rs0 = ks + 128 * QST;      // 256
    float* ws0 = rs0 + 256;           // 256
    float* rs1 = ws0 + 256;           // 256
    float* ws1 = rs1 + 256;           // 256
    float* bgs = ws1 + 256;           // 64
    float* bos = bgs + HD;            // 128

    const int tid  = threadIdx.x;
    const int lane = tid & 31;
    const int wid  = tid >> 5;
    const int mt   = wid & 3;         // m-tile (16 rows)
    const int nq   = wid >> 2;        // n quarter (32 cols)
    const int gid  = lane >> 2;
    const int tig  = lane & 3;
    const long base = (long)blockIdx.x * P;

    if (tid < HD)  bgs[tid] = bg[tid];
    else if (tid >= 64 && tid < 64 + CZ) bos[tid - 64] = bo[tid - 64];

    const int c4 = lane * 4;
    const float4 gp = *(const float4*)(lpg + c4), bp = *(const float4*)(lpb + c4);
    const float4 gt = *(const float4*)(ltg + c4), bt = *(const float4*)(ltb + c4);

    // ---------------- Phase A: LN(pair)->xs0, Wq|Wg, QG GEMM ----------------
    ln64(pair, base, R, xs0, gp, bp, wid, lane);
    stageW2(wt, Wq, Wg, tid);
    __syncthreads();

    float g[4][4];                    // meaningful on nq>=2 warps
    {
        float qga[4][4] = {};
        gemm_warp(qga, xs0, XST, wt, mt, nq, gid, tig, 16);
        if (nq < 2) {                 // Q -> smem (plain cols)
            const int p0 = mt * 16 + gid, p1 = p0 + 8;
            #pragma unroll
            for (int nt = 0; nt < 4; nt++) {
                const int c = nq * 32 + nt * 8 + tig * 2;
                qs[p0 * QST + c]     = qga[nt][0];
                qs[p0 * QST + c + 1] = qga[nt][1];
                qs[p1 * QST + c]     = qga[nt][2];
                qs[p1 * QST + c + 1] = qga[nt][3];
            }
        } else {                      // G kept in fragments
            #pragma unroll
            for (int nt = 0; nt < 4; nt++) {
                const int c = (nq - 2) * 32 + nt * 8 + tig * 2;
                g[nt][0] = 1.f / (1.f + __expf(-(qga[nt][0] + bgs[c])));
                g[nt][1] = 1.f / (1.f + __expf(-(qga[nt][1] + bgs[c + 1])));
                g[nt][2] = 1.f / (1.f + __expf(-(qga[nt][2] + bgs[c])));
                g[nt][3] = 1.f / (1.f + __expf(-(qga[nt][3] + bgs[c + 1])));
            }
        }
    }
    __syncthreads();                  // QG GEMM done -> xs0 reusable

    // Wk|Wv, LN of first template pair, Q into score-thread registers
    stageW2(wt, Wk, Wv, tid);
    ln64(tmpl, base, R, xs0, gt, bt, wid, lane);
    if (T > 1) ln64(tmpl + (long)R * CZ, base, R, xs1, gt, bt, wid, lane);

    float qreg[16];
    float m_run = __int_as_float(0xff800000), l_run = 0.f;
    if (tid < 256) {
        const int sp = tid >> 2, sh = tid & 3;
        const float4* qp = (const float4*)(qs + sp * QST + sh * 16);
        #pragma unroll
        for (int qd = 0; qd < 4; qd++) {
            float4 v = qp[qd];
            qreg[qd * 4 + 0] = v.x; qreg[qd * 4 + 1] = v.y;
            qreg[qd * 4 + 2] = v.z; qreg[qd * 4 + 3] = v.w;
        }
    }
    float vAcc[4][4] = {};
    __syncthreads();

    // ---------------- pair loop: 2 templates per trip, 2 syncs ----------------
    const int NP = (T + 1) >> 1;
    #pragma unroll 1
    for (int pr = 0; pr < NP; pr++) {
        const bool doT1 = (2 * pr + 1) < T;
        float kv0[4][4] = {}, kv1[4][4] = {};
        gemm_pair(kv0, kv1, xs0, xs1, wt, mt, nq, gid, tig, doT1);
        if (nq < 2) {                 // K (both templates) -> ks
            const int p0 = mt * 16 + gid, p1 = p0 + 8;
            #pragma unroll
            for (int nt = 0; nt < 4; nt++) {
                const int c = nq * 32 + nt * 8 + tig * 2;
                ks[p0 * QST + c]           = kv0[nt][0];
                ks[p0 * QST + c + 1]       = kv0[nt][1];
                ks[p1 * QST + c]           = kv0[nt][2];
                ks[p1 * QST + c + 1]       = kv0[nt][3];
                ks[(p0 + 64) * QST + c]     = kv1[nt][0];
                ks[(p0 + 64) * QST + c + 1] = kv1[nt][1];
                ks[(p1 + 64) * QST + c]     = kv1[nt][2];
                ks[(p1 + 64) * QST + c + 1] = kv1[nt][3];
            }
        }
        __syncthreads();              // S1: ks ready; prev V-acc done

        if (tid < 256) {              // scores for both templates, thread owns (p,h)
            const int sp = tid >> 2, sh = tid & 3;
            const float4* k0p = (const float4*)(ks + sp * QST + sh * 16);
            const float4* k1p = (const float4*)(ks + (sp + 64) * QST + sh * 16);
            float s0 = 0.f, s1 = 0.f;
            #pragma unroll
            for (int qd = 0; qd < 4; qd++) {
                float4 kq0 = k0p[qd], kq1 = k1p[qd];
                s0 = fmaf(qreg[qd * 4 + 0], kq0.x, s0);
                s0 = fmaf(qreg[qd * 4 + 1], kq0.y, s0);
                s0 = fmaf(qreg[qd * 4 + 2], kq0.z, s0);
                s0 = fmaf(qreg[qd * 4 + 3], kq0.w, s0);
                s1 = fmaf(qreg[qd * 4 + 0], kq1.x, s1);
                s1 = fmaf(qreg[qd * 4 + 1], kq1.y, s1);
                s1 = fmaf(qreg[qd * 4 + 2], kq1.z, s1);
                s1 = fmaf(qreg[qd * 4 + 3], kq1.w, s1);
            }
            s0 *= 0.25f; s1 *= 0.25f; // 1/sqrt(D=16)
            float mn0 = fmaxf(m_run, s0);
            float rr0 = __expf(m_run - mn0);
            float ww0 = __expf(s0 - mn0);
            l_run = l_run * rr0 + ww0;
            m_run = mn0;
            float rr1 = 1.f, ww1 = 0.f;
            if (doT1) {
                float mn1 = fmaxf(m_run, s1);
                rr1 = __expf(m_run - mn1);
                ww1 = __expf(s1 - mn1);
                l_run = l_run * rr1 + ww1;
                m_run = mn1;
            }
            rs0[tid] = rr0; ws0[tid] = ww0;
            rs1[tid] = rr1; ws1[tid] = ww1;
        }
        if (2 * pr + 2 < T)
            ln64(tmpl + (long)(2 * pr + 2) * R * CZ, base, R, xs0, gt, bt, wid, lane);
        if (2 * pr + 3 < T)
            ln64(tmpl + (long)(2 * pr + 3) * R * CZ, base, R, xs1, gt, bt, wid, lane);
        __syncthreads();              // S2: rs/ws + next xs ready

        if (nq >= 2) {                // V online accumulate, both templates
            const int p0 = mt * 16 + gid, p1 = p0 + 8;
            const int hb = (nq - 2) * 2;
            #pragma unroll
            for (int nt = 0; nt < 4; nt++) {
                const int h = hb + (nt >> 1);
                float rr00 = rs0[p0 * 4 + h], ww00 = ws0[p0 * 4 + h];
                float rr01 = rs0[p1 * 4 + h], ww01 = ws0[p1 * 4 + h];
                float rr10 = rs1[p0 * 4 + h], ww10 = ws1[p0 * 4 + h];
                float rr11 = rs1[p1 * 4 + h], ww11 = ws1[p1 * 4 + h];
                vAcc[nt][0] = fmaf(fmaf(vAcc[nt][0], rr00, ww00 * kv0[nt][0]), rr10, ww10 * kv1[nt][0]);
                vAcc[nt][1] = fmaf(fmaf(vAcc[nt][1], rr00, ww00 * kv0[nt][1]), rr10, ww10 * kv1[nt][1]);
                vAcc[nt][2] = fmaf(fmaf(vAcc[nt][2], rr01, ww01 * kv0[nt][2]), rr11, ww11 * kv1[nt][2]);
                vAcc[nt][3] = fmaf(fmaf(vAcc[nt][3], rr01, ww01 * kv0[nt][3]), rr11, ww11 * kv1[nt][3]);
            }
        }
        // no sync: V-acc finishes before this warp reaches S1 of next trip
    }
    __syncthreads();                  // all V-acc done; rs0/ks reusable

    // ---------------- Phase C: finalize, Wo, O GEMM ----------------
    if (tid < 256) rs0[tid] = 1.f / l_run;      // linv per (p,h)
    {   // stage Wo[k=64][n=128] -> wt[n][kperm]
        #pragma unroll 1
        for (int i = tid; i < 2048; i += NT) {
            const int k = i >> 5, ng = i & 31;
            float4 w = *(const float4*)(Wo + k * CZ + ng * 4);
            const int n  = ng * 4;
            const int pk = kperm(k);
            wt[(n + 0) * XST + pk] = tf32r(w.x);
            wt[(n + 1) * XST + pk] = tf32r(w.y);
            wt[(n + 2) * XST + pk] = tf32r(w.z);
            wt[(n + 3) * XST + pk] = tf32r(w.w);
        }
    }
    __syncthreads();

    if (nq >= 2) {                    // vals = vAcc * G * linv -> ks (kperm cols)
        const int p0 = mt * 16 + gid, p1 = p0 + 8;
        const int hb = (nq - 2) * 2;
        #pragma unroll
        for (int nt = 0; nt < 4; nt++) {
            const int c  = (nq - 2) * 32 + nt * 8 + tig * 2;
            const int pc = kperm(c);  // kperm(c+1) == pc+2 for even c with c&3 in {0,2}
            const int h  = hb + (nt >> 1);
            float li0 = rs0[p0 * 4 + h], li1 = rs0[p1 * 4 + h];
            ks[p0 * QST + pc]     = tf32r(vAcc[nt][0] * g[nt][0] * li0);
            ks[p0 * QST + pc + 2] = tf32r(vAcc[nt][1] * g[nt][1] * li0);
            ks[p1 * QST + pc]     = tf32r(vAcc[nt][2] * g[nt][2] * li1);
            ks[p1 * QST + pc + 2] = tf32r(vAcc[nt][3] * g[nt][3] * li1);
        }
    }
    __syncthreads();

    {
        float oc[4][4] = {};
        gemm_warp(oc, ks, QST, wt, mt, nq, gid, tig, 8);
        const long r0 = base + mt * 16 + gid, r1 = r0 + 8;
        #pragma unroll
        for (int nt = 0; nt < 4; nt++) {
            const int c = nq * 32 + nt * 8 + tig * 2;
            if (r0 < R) {
                float2 v = make_float2(oc[nt][0] + bos[c], oc[nt][1] + bos[c + 1]);
                *(float2*)(out + r0 * (long)CZ + c) = v;
            }
            if (r1 < R) {
                float2 v = make_float2(oc[nt][2] + bos[c], oc[nt][3] + bos[c + 1]);
                *(float2*)(out + r1 * (long)CZ + c) = v;
            }
        }
    }
}

extern "C" void kernel_launch(void* const* d_in, const int* in_sizes, int n_in,
                              void* d_out, int out_size)
{
    const float* tmpl = (const float*)d_in[0];
    const float* pair = (const float*)d_in[1];
    const float* lpg  = (const float*)d_in[2];
    const float* lpb  = (const float*)d_in[3];
    const float* ltg  = (const float*)d_in[4];
    const float* ltb  = (const float*)d_in[5];
    const float* Wq   = (const float*)d_in[6];
    const float* Wk   = (const float*)d_in[7];
    const float* Wv   = (const float*)d_in[8];
    const float* Wg   = (const float*)d_in[9];
    const float* bg   = (const float*)d_in[10];
    const float* Wo   = (const float*)d_in[11];
    const float* bo   = (const float*)d_in[12];
    float* out = (float*)d_out;

    const int R = in_sizes[1] / CZ;           // b*n*n pixels
    const int T = in_sizes[0] / in_sizes[1];  // templates

    const size_t smem = (size_t)(2 * P * XST + 128 * XST + P * QST + 128 * QST
                                 + 4 * 256 + HD + CZ) * sizeof(float);
    cudaFuncSetAttribute(tpa_mma4, cudaFuncAttributeMaxDynamicSharedMemorySize, (int)smem);

    const int grid = (R + P - 1) / P;
    tpa_mma4<<<grid, NT, smem>>>(tmpl, pair, lpg, lpb, ltg, ltb,
                                 Wq, Wk, Wv, Wg, bg, Wo, bo, out, R, T);
}

// round 7
// speedup vs baseline: 1.4221x; 1.3720x over previous
#include <cuda_runtime.h>
#include <cstdint>

#define CZ  128
#define HD  64
#define P   128     // pixels per CTA
#define NT  512
#define NW  16
#define XST 132     // [row][k] stride: scalar LDS banks 4*gid+tig -> conflict-free
#define QST 68      // [row][c] stride: mult of 4 (float4), O-GEMM A loads conflict-free

static __device__ __forceinline__ float tf32r(float x) {
    float y; asm("cvt.rna.tf32.f32 %0, %1;" : "=f"(y) : "f"(x)); return y;
}

static __device__ __forceinline__ void mma8(float* d,
    float a0, float a1, float a2, float a3, float b0, float b1)
{
    asm volatile("mma.sync.aligned.m16n8k8.row.col.f32.tf32.tf32.f32 "
        "{%0,%1,%2,%3}, {%4,%5,%6,%7}, {%8,%9}, {%0,%1,%2,%3};"
        : "+f"(d[0]), "+f"(d[1]), "+f"(d[2]), "+f"(d[3])
        : "r"(__float_as_uint(a0)), "r"(__float_as_uint(a1)),
          "r"(__float_as_uint(a2)), "r"(__float_as_uint(a3)),
          "r"(__float_as_uint(b0)), "r"(__float_as_uint(b1)));
}

// Warp computes 32 rows (mt) x 32 cols (nq); K = 8*KT.
// A [row][k] stride ast; B wt[n][k] stride XST. 16 LDS feed 8 MMAs per kt.
static __device__ __forceinline__ void gemm32(
    float acc[2][4][4], const float* A, int ast, const float* wt,
    int mt, int nq, int gid, int tig, int KT)
{
    const float* ar0 = A + (mt * 32 + gid) * ast + tig;
    const float* ar1 = ar0 + 8 * ast;
    const float* ar2 = ar0 + 16 * ast;
    const float* ar3 = ar0 + 24 * ast;
    const float* bp  = wt + (nq * 32 + gid) * XST + tig;
    #pragma unroll 4
    for (int kt = 0; kt < KT; kt++) {
        const int k0 = kt * 8;
        float a00 = ar0[k0], a01 = ar1[k0], a02 = ar0[k0 + 4], a03 = ar1[k0 + 4];
        float a10 = ar2[k0], a11 = ar3[k0], a12 = ar2[k0 + 4], a13 = ar3[k0 + 4];
        #pragma unroll
        for (int nt = 0; nt < 4; nt++) {
            float b0 = bp[nt * 8 * XST + k0];
            float b1 = bp[nt * 8 * XST + k0 + 4];
            mma8(acc[0][nt], a00, a01, a02, a03, b0, b1);
            mma8(acc[1][nt], a10, a11, a12, a13, b0, b1);
        }
    }
}

// LayerNorm 128 rows x 128 cols -> tf32 into [row][k] stride XST.
static __device__ __forceinline__ void ln128(
    const float* __restrict__ src, long base, int R, float* dst,
    float4 g4, float4 b4, int wid, int lane)
{
    const int c4 = lane * 4;
    #pragma unroll
    for (int r = wid; r < P; r += NW) {
        long row = base + r;
        float4 x = make_float4(0.f, 0.f, 0.f, 0.f);
        if (row < R) x = *(const float4*)(src + row * (long)CZ + c4);
        float s = x.x + x.y + x.z + x.w;
        float q = fmaf(x.x, x.x, fmaf(x.y, x.y, fmaf(x.z, x.z, x.w * x.w)));
        #pragma unroll
        for (int o = 16; o; o >>= 1) {
            s += __shfl_xor_sync(0xffffffffu, s, o);
            q += __shfl_xor_sync(0xffffffffu, q, o);
        }
        float m  = s * (1.f / CZ);
        float v  = fmaxf(q * (1.f / CZ) - m * m, 0.f);
        float ri = rsqrtf(v + 1e-5f);
        float* xr = dst + r * XST + c4;
        xr[0] = tf32r((x.x - m) * ri * g4.x + b4.x);
        xr[1] = tf32r((x.y - m) * ri * g4.y + b4.y);
        xr[2] = tf32r((x.z - m) * ri * g4.z + b4.z);
        xr[3] = tf32r((x.w - m) * ri * g4.w + b4.w);
    }
}

// Stage two k-major [128][64] weights into wt[n][k] (n<64: W1, else W2).
static __device__ __forceinline__ void stageW2(
    float* wt, const float* __restrict__ W1, const float* __restrict__ W2, int tid)
{
    #pragma unroll 1
    for (int i = tid; i < 4096; i += NT) {
        const int m  = i >> 11;
        const int k  = (i >> 4) & 127;
        const int ng = i & 15;
        const float* Ws = m ? W2 : W1;
        float4 w = *(const float4*)(Ws + k * HD + ng * 4);
        const int n = m * 64 + ng * 4;
        wt[(n + 0) * XST + k] = tf32r(w.x);
        wt[(n + 1) * XST + k] = tf32r(w.y);
        wt[(n + 2) * XST + k] = tf32r(w.z);
        wt[(n + 3) * XST + k] = tf32r(w.w);
    }
}

__global__ void __launch_bounds__(NT, 1)
tpa_mma5(const float* __restrict__ tmpl, const float* __restrict__ pair,
         const float* __restrict__ lpg, const float* __restrict__ lpb,
         const float* __restrict__ ltg, const float* __restrict__ ltb,
         const float* __restrict__ Wq,  const float* __restrict__ Wk,
         const float* __restrict__ Wv,  const float* __restrict__ Wg,
         const float* __restrict__ bg,  const float* __restrict__ Wo,
         const float* __restrict__ bo,  float* __restrict__ out,
         int R, int T)
{
    extern __shared__ float smf[];
    float* xs  = smf;                 // 128 x XST : LN'd activations (single buffer)
    float* wt  = xs + P * XST;        // 128 x XST : weights [n][k]
    float* ks  = wt + 128 * XST;      // 128 x QST : Q, then K_t, then vals
    float* gs  = ks + P * QST;        // 128 x QST : G gate
    float* rs  = gs + P * QST;        // 512 : rescale / 1/l  (indexed p*4+h)
    float* ws  = rs + 512;            // 512 : new weight
    float* bgs = ws + 512;            // 64
    float* bos = bgs + HD;            // 128

    const int tid  = threadIdx.x;
    const int lane = tid & 31;
    const int wid  = tid >> 5;
    const int mt   = wid & 3;         // m-tile (32 rows)
    const int nq   = wid >> 2;        // n quarter (32 cols)
    const int gid  = lane >> 2;
    const int tig  = lane & 3;
    const long base = (long)blockIdx.x * P;

    if (tid < HD)  bgs[tid] = bg[tid];
    else if (tid >= 64 && tid < 64 + CZ) bos[tid - 64] = bo[tid - 64];

    const int c4 = lane * 4;
    const float4 gp = *(const float4*)(lpg + c4), bp = *(const float4*)(lpb + c4);
    const float4 gt = *(const float4*)(ltg + c4), bt = *(const float4*)(ltb + c4);

    // ---------------- Phase A: LN(pair)->xs, Wq|Wg, QG GEMM ----------------
    ln128(pair, base, R, xs, gp, bp, wid, lane);
    stageW2(wt, Wq, Wg, tid);
    __syncthreads();

    {
        float qga[2][4][4] = {};
        gemm32(qga, xs, XST, wt, mt, nq, gid, tig, 16);
        if (nq < 2) {                 // Q -> ks
            #pragma unroll
            for (int f = 0; f < 2; f++) {
                const int r0 = mt * 32 + f * 16 + gid, r1 = r0 + 8;
                #pragma unroll
                for (int nt = 0; nt < 4; nt++) {
                    const int c = nq * 32 + nt * 8 + tig * 2;
                    ks[r0 * QST + c]     = qga[f][nt][0];
                    ks[r0 * QST + c + 1] = qga[f][nt][1];
                    ks[r1 * QST + c]     = qga[f][nt][2];
                    ks[r1 * QST + c + 1] = qga[f][nt][3];
                }
            }
        } else {                      // G -> gs (sigmoid)
            #pragma unroll
            for (int f = 0; f < 2; f++) {
                const int r0 = mt * 32 + f * 16 + gid, r1 = r0 + 8;
                #pragma unroll
                for (int nt = 0; nt < 4; nt++) {
                    const int c = (nq - 2) * 32 + nt * 8 + tig * 2;
                    gs[r0 * QST + c]     = 1.f / (1.f + __expf(-(qga[f][nt][0] + bgs[c])));
                    gs[r0 * QST + c + 1] = 1.f / (1.f + __expf(-(qga[f][nt][1] + bgs[c + 1])));
                    gs[r1 * QST + c]     = 1.f / (1.f + __expf(-(qga[f][nt][2] + bgs[c])));
                    gs[r1 * QST + c + 1] = 1.f / (1.f + __expf(-(qga[f][nt][3] + bgs[c + 1])));
                }
            }
        }
    }
    __syncthreads();                  // Q in ks; xs/wt free

    // score threads (tid<256) own (p0 = tid>>2, h = tid&3) and (p1 = p0+64, h)
    float qreg[32];
    float m0 = __int_as_float(0xff800000), l0 = 0.f;
    float m1 = __int_as_float(0xff800000), l1 = 0.f;
    if (tid < 256) {
        const int sp = tid >> 2, sh = tid & 3;
        const float4* q0 = (const float4*)(ks + sp * QST + sh * 16);
        const float4* q1 = (const float4*)(ks + (sp + 64) * QST + sh * 16);
        #pragma unroll
        for (int qd = 0; qd < 4; qd++) {
            float4 v0 = q0[qd], v1 = q1[qd];
            qreg[qd * 4 + 0]  = v0.x; qreg[qd * 4 + 1]  = v0.y;
            qreg[qd * 4 + 2]  = v0.z; qreg[qd * 4 + 3]  = v0.w;
            qreg[16 + qd * 4 + 0] = v1.x; qreg[16 + qd * 4 + 1] = v1.y;
            qreg[16 + qd * 4 + 2] = v1.z; qreg[16 + qd * 4 + 3] = v1.w;
        }
    }
    stageW2(wt, Wk, Wv, tid);
    ln128(tmpl, base, R, xs, gt, bt, wid, lane);    // LN(t=0)
    float vAcc[2][4][4] = {};
    __syncthreads();                  // qreg captured -> ks free; xs/wt ready

    // ---------------- template loop: 2 syncs per t ----------------
    #pragma unroll 1
    for (int t = 0; t < T; t++) {
        float kv[2][4][4] = {};
        gemm32(kv, xs, XST, wt, mt, nq, gid, tig, 16);
        if (nq < 2) {                 // K -> ks
            #pragma unroll
            for (int f = 0; f < 2; f++) {
                const int r0 = mt * 32 + f * 16 + gid, r1 = r0 + 8;
                #pragma unroll
                for (int nt = 0; nt < 4; nt++) {
                    const int c = nq * 32 + nt * 8 + tig * 2;
                    ks[r0 * QST + c]     = kv[f][nt][0];
                    ks[r0 * QST + c + 1] = kv[f][nt][1];
                    ks[r1 * QST + c]     = kv[f][nt][2];
                    ks[r1 * QST + c + 1] = kv[f][nt][3];
                }
            }
        }
        __syncthreads();              // S1: ks ready; xs read done; prev V-acc done

        if (tid < 256) {              // scores + online softmax for 2 (p,h) pairs
            const int sp = tid >> 2, sh = tid & 3;
            const float4* k0p = (const float4*)(ks + sp * QST + sh * 16);
            const float4* k1p = (const float4*)(ks + (sp + 64) * QST + sh * 16);
            float s0 = 0.f, s1 = 0.f;
            #pragma unroll
            for (int qd = 0; qd < 4; qd++) {
                float4 k0 = k0p[qd], k1 = k1p[qd];
                s0 = fmaf(qreg[qd * 4 + 0], k0.x, s0);
                s0 = fmaf(qreg[qd * 4 + 1], k0.y, s0);
                s0 = fmaf(qreg[qd * 4 + 2], k0.z, s0);
                s0 = fmaf(qreg[qd * 4 + 3], k0.w, s0);
                s1 = fmaf(qreg[16 + qd * 4 + 0], k1.x, s1);
                s1 = fmaf(qreg[16 + qd * 4 + 1], k1.y, s1);
                s1 = fmaf(qreg[16 + qd * 4 + 2], k1.z, s1);
                s1 = fmaf(qreg[16 + qd * 4 + 3], k1.w, s1);
            }
            s0 *= 0.25f; s1 *= 0.25f; // 1/sqrt(D=16)
            float mn0 = fmaxf(m0, s0);
            float rr0 = __expf(m0 - mn0), ww0 = __expf(s0 - mn0);
            l0 = l0 * rr0 + ww0; m0 = mn0;
            float mn1 = fmaxf(m1, s1);
            float rr1 = __expf(m1 - mn1), ww1 = __expf(s1 - mn1);
            l1 = l1 * rr1 + ww1; m1 = mn1;
            rs[tid]       = rr0; ws[tid]       = ww0;
            rs[tid + 256] = rr1; ws[tid + 256] = ww1;
        }
        if (t + 1 < T)                // LN(t+1) overwrites xs (read finished pre-S1)
            ln128(tmpl + (long)(t + 1) * R * CZ, base, R, xs, gt, bt, wid, lane);
        __syncthreads();              // S2: rs/ws + xs(t+1) ready

        if (nq >= 2) {                // V online accumulate in fragments
            #pragma unroll
            for (int f = 0; f < 2; f++) {
                const int r0 = mt * 32 + f * 16 + gid, r1 = r0 + 8;
                #pragma unroll
                for (int nt = 0; nt < 4; nt++) {
                    const int h = ((nq - 2) * 32 + nt * 8) >> 4;   // head of this col group
                    float rr0 = rs[r0 * 4 + h], ww0 = ws[r0 * 4 + h];
                    float rr1 = rs[r1 * 4 + h], ww1 = ws[r1 * 4 + h];
                    vAcc[f][nt][0] = fmaf(vAcc[f][nt][0], rr0, ww0 * kv[f][nt][0]);
                    vAcc[f][nt][1] = fmaf(vAcc[f][nt][1], rr0, ww0 * kv[f][nt][1]);
                    vAcc[f][nt][2] = fmaf(vAcc[f][nt][2], rr1, ww1 * kv[f][nt][2]);
                    vAcc[f][nt][3] = fmaf(vAcc[f][nt][3], rr1, ww1 * kv[f][nt][3]);
                }
            }
        }
        // no trailing sync: V-acc (reads rs/ws) completes before this warp passes
        // S1 of next trip; rs/ws rewritten only after that barrier.
    }
    __syncthreads();                  // all V-acc done; rs/ks reusable

    // ---------------- Phase C: finalize, Wo, vals, O GEMM ----------------
    if (tid < 256) {                  // linv per (p,h)
        rs[tid]       = 1.f / l0;
        rs[tid + 256] = 1.f / l1;
    }
    {   // stage Wo[k=64][n=128] -> wt[n][k]
        #pragma unroll 1
        for (int i = tid; i < 2048; i += NT) {
            const int k = i >> 5, ng = i & 31;
            float4 w = *(const float4*)(Wo + k * CZ + ng * 4);
            const int n = ng * 4;
            wt[(n + 0) * XST + k] = tf32r(w.x);
            wt[(n + 1) * XST + k] = tf32r(w.y);
            wt[(n + 2) * XST + k] = tf32r(w.z);
            wt[(n + 3) * XST + k] = tf32r(w.w);
        }
    }
    __syncthreads();

    if (nq >= 2) {                    // vals = vAcc * G * linv -> ks
        #pragma unroll
        for (int f = 0; f < 2; f++) {
            const int r0 = mt * 32 + f * 16 + gid, r1 = r0 + 8;
            #pragma unroll
            for (int nt = 0; nt < 4; nt++) {
                const int c = (nq - 2) * 32 + nt * 8 + tig * 2;
                const int h = ((nq - 2) * 32 + nt * 8) >> 4;
                float li0 = rs[r0 * 4 + h], li1 = rs[r1 * 4 + h];
                ks[r0 * QST + c]     = tf32r(vAcc[f][nt][0] * gs[r0 * QST + c]     * li0);
                ks[r0 * QST + c + 1] = tf32r(vAcc[f][nt][1] * gs[r0 * QST + c + 1] * li0);
                ks[r1 * QST + c]     = tf32r(vAcc[f][nt][2] * gs[r1 * QST + c]     * li1);
                ks[r1 * QST + c + 1] = tf32r(vAcc[f][nt][3] * gs[r1 * QST + c + 1] * li1);
            }
        }
    }
    __syncthreads();

    {
        float oc[2][4][4] = {};
        gemm32(oc, ks, QST, wt, mt, nq, gid, tig, 8);
        #pragma unroll
        for (int f = 0; f < 2; f++) {
            const long r0 = base + mt * 32 + f * 16 + gid, r1 = r0 + 8;
            #pragma unroll
            for (int nt = 0; nt < 4; nt++) {
                const int c = nq * 32 + nt * 8 + tig * 2;
                if (r0 < R) {
                    float2 v = make_float2(oc[f][nt][0] + bos[c], oc[f][nt][1] + bos[c + 1]);
                    *(float2*)(out + r0 * (long)CZ + c) = v;
                }
                if (r1 < R) {
                    float2 v = make_float2(oc[f][nt][2] + bos[c], oc[f][nt][3] + bos[c + 1]);
                    *(float2*)(out + r1 * (long)CZ + c) = v;
                }
            }
        }
    }
}

extern "C" void kernel_launch(void* const* d_in, const int* in_sizes, int n_in,
                              void* d_out, int out_size)
{
    const float* tmpl = (const float*)d_in[0];
    const float* pair = (const float*)d_in[1];
    const float* lpg  = (const float*)d_in[2];
    const float* lpb  = (const float*)d_in[3];
    const float* ltg  = (const float*)d_in[4];
    const float* ltb  = (const float*)d_in[5];
    const float* Wq   = (const float*)d_in[6];
    const float* Wk   = (const float*)d_in[7];
    const float* Wv   = (const float*)d_in[8];
    const float* Wg   = (const float*)d_in[9];
    const float* bg   = (const float*)d_in[10];
    const float* Wo   = (const float*)d_in[11];
    const float* bo   = (const float*)d_in[12];
    float* out = (float*)d_out;

    const int R = in_sizes[1] / CZ;           // b*n*n pixels
    const int T = in_sizes[0] / in_sizes[1];  // templates

    const size_t smem = (size_t)(P * XST + 128 * XST + 2 * P * QST
                                 + 2 * 512 + HD + CZ) * sizeof(float);
    cudaFuncSetAttribute(tpa_mma5, cudaFuncAttributeMaxDynamicSharedMemorySize, (int)smem);

    const int grid = (R + P - 1) / P;
    tpa_mma5<<<grid, NT, smem>>>(tmpl, pair, lpg, lpb, ltg, ltb,
                                 Wq, Wk, Wv, Wg, bg, Wo, bo, out, R, T);
}

// round 8
// speedup vs baseline: 1.6037x; 1.1277x over previous
#include <cuda_runtime.h>
#include <cstdint>

#define CZ  128
#define HD  64
#define P   128     // pixels per CTA
#define NT  512
#define XST 132     // [row][k] stride: scalar LDS banks 4*gid+tig -> conflict-free

static __device__ __forceinline__ float tf32r(float x) {
    float y; asm("cvt.rna.tf32.f32 %0, %1;" : "=f"(y) : "f"(x)); return y;
}

static __device__ __forceinline__ void mma8(float* d,
    float a0, float a1, float a2, float a3, float b0, float b1)
{
    asm volatile("mma.sync.aligned.m16n8k8.row.col.f32.tf32.tf32.f32 "
        "{%0,%1,%2,%3}, {%4,%5,%6,%7}, {%8,%9}, {%0,%1,%2,%3};"
        : "+f"(d[0]), "+f"(d[1]), "+f"(d[2]), "+f"(d[3])
        : "r"(__float_as_uint(a0)), "r"(__float_as_uint(a1)),
          "r"(__float_as_uint(a2)), "r"(__float_as_uint(a3)),
          "r"(__float_as_uint(b0)), "r"(__float_as_uint(b1)));
}

// Warp computes 32 rows (mt) x 32 cols (nq); K = 8*KT.
static __device__ __forceinline__ void gemm32(
    float acc[2][4][4], const float* A, int ast, const float* wt,
    int mt, int nq, int gid, int tig, int KT)
{
    const float* ar0 = A + (mt * 32 + gid) * ast + tig;
    const float* ar1 = ar0 + 8 * ast;
    const float* ar2 = ar0 + 16 * ast;
    const float* ar3 = ar0 + 24 * ast;
    const float* bp  = wt + (nq * 32 + gid) * XST + tig;
    #pragma unroll 4
    for (int kt = 0; kt < KT; kt++) {
        const int k0 = kt * 8;
        float a00 = ar0[k0], a01 = ar1[k0], a02 = ar0[k0 + 4], a03 = ar1[k0 + 4];
        float a10 = ar2[k0], a11 = ar3[k0], a12 = ar2[k0 + 4], a13 = ar3[k0 + 4];
        #pragma unroll
        for (int nt = 0; nt < 4; nt++) {
            float b0 = bp[nt * 8 * XST + k0];
            float b1 = bp[nt * 8 * XST + k0 + 4];
            mma8(acc[0][nt], a00, a01, a02, a03, b0, b1);
            mma8(acc[1][nt], a10, a11, a12, a13, b0, b1);
        }
    }
}

// LayerNorm rows r0, r0+step, ... of a 128x128 block -> tf32 [row][k] stride XST.
static __device__ __forceinline__ void ln128s(
    const float* __restrict__ src, long base, int R, float* dst,
    float4 g4, float4 b4, int r0, int step, int lane)
{
    const int c4 = lane * 4;
    #pragma unroll
    for (int r = r0; r < P; r += step) {
        long row = base + r;
        float4 x = make_float4(0.f, 0.f, 0.f, 0.f);
        if (row < R) x = *(const float4*)(src + row * (long)CZ + c4);
        float s = x.x + x.y + x.z + x.w;
        float q = fmaf(x.x, x.x, fmaf(x.y, x.y, fmaf(x.z, x.z, x.w * x.w)));
        #pragma unroll
        for (int o = 16; o; o >>= 1) {
            s += __shfl_xor_sync(0xffffffffu, s, o);
            q += __shfl_xor_sync(0xffffffffu, q, o);
        }
        float m  = s * (1.f / CZ);
        float v  = fmaxf(q * (1.f / CZ) - m * m, 0.f);
        float ri = rsqrtf(v + 1e-5f);
        float* xr = dst + r * XST + c4;
        xr[0] = tf32r((x.x - m) * ri * g4.x + b4.x);
        xr[1] = tf32r((x.y - m) * ri * g4.y + b4.y);
        xr[2] = tf32r((x.z - m) * ri * g4.z + b4.z);
        xr[3] = tf32r((x.w - m) * ri * g4.w + b4.w);
    }
}

// Stage two k-major [128][64] weights into wt[n][k] (n<64: W1, else W2).
static __device__ __forceinline__ void stageW2(
    float* wt, const float* __restrict__ W1, const float* __restrict__ W2, int tid)
{
    #pragma unroll 1
    for (int i = tid; i < 4096; i += NT) {
        const int m  = i >> 11;
        const int k  = (i >> 4) & 127;
        const int ng = i & 15;
        const float* Ws = m ? W2 : W1;
        float4 w = *(const float4*)(Ws + k * HD + ng * 4);
        const int n = m * 64 + ng * 4;
        wt[(n + 0) * XST + k] = tf32r(w.x);
        wt[(n + 1) * XST + k] = tf32r(w.y);
        wt[(n + 2) * XST + k] = tf32r(w.z);
        wt[(n + 3) * XST + k] = tf32r(w.w);
    }
}

__global__ void __launch_bounds__(NT, 1)
tpa_mma6(const float* __restrict__ tmpl, const float* __restrict__ pair,
         const float* __restrict__ lpg, const float* __restrict__ lpb,
         const float* __restrict__ ltg, const float* __restrict__ ltb,
         const float* __restrict__ Wq,  const float* __restrict__ Wk,
         const float* __restrict__ Wv,  const float* __restrict__ Wg,
         const float* __restrict__ bg,  const float* __restrict__ Wo,
         const float* __restrict__ bo,  float* __restrict__ out,
         int R, int T)
{
    extern __shared__ float smf[];
    float* xs0 = smf;                 // 128 x XST : LN buffer A (also vals later)
    float* xs1 = xs0 + P * XST;       // 128 x XST : LN buffer B
    float* wt  = xs1 + P * XST;       // 128 x XST : weights [n][k]
    float* rs  = wt + 128 * XST;      // 512 : softmax rescale   (p*4+h)
    float* ws  = rs + 512;            // 512 : softmax new weight
    float* ls  = ws + 512;            // 512 : 1/l
    float* bgs = ls + 512;            // 64
    float* bos = bgs + HD;            // 128

    const int tid  = threadIdx.x;
    const int lane = tid & 31;
    const int wid  = tid >> 5;
    const int mt   = wid & 3;         // m-tile (32 rows)
    const int nq   = wid >> 2;        // n quarter (32 cols)
    const int gid  = lane >> 2;
    const int tig  = lane & 3;
    const bool isK = (nq < 2);        // K-warps own Q/K cols; V-warps own G/V cols
    const long base = (long)blockIdx.x * P;

    if (tid < HD)  bgs[tid] = bg[tid];
    else if (tid >= 64 && tid < 64 + CZ) bos[tid - 64] = bo[tid - 64];

    const int c4 = lane * 4;
    const float4 gp = *(const float4*)(lpg + c4), bp = *(const float4*)(lpb + c4);
    const float4 gt = *(const float4*)(ltg + c4), bt = *(const float4*)(ltb + c4);

    // ---------------- Phase A: LN(pair)->xs0, Wq|Wg, QG GEMM ----------------
    ln128s(pair, base, R, xs0, gp, bp, wid, 16, lane);
    stageW2(wt, Wq, Wg, tid);
    __syncthreads();

    float qf[2][4][4] = {};           // K-warps: Q fragments; V-warps: G after sigmoid
    gemm32(qf, xs0, XST, wt, mt, nq, gid, tig, 16);
    if (!isK) {                       // sigmoid in place -> qf holds G
        #pragma unroll
        for (int f = 0; f < 2; f++)
            #pragma unroll
            for (int nt = 0; nt < 4; nt++) {
                const int c = (nq - 2) * 32 + nt * 8 + tig * 2;
                qf[f][nt][0] = 1.f / (1.f + __expf(-(qf[f][nt][0] + bgs[c])));
                qf[f][nt][1] = 1.f / (1.f + __expf(-(qf[f][nt][1] + bgs[c + 1])));
                qf[f][nt][2] = 1.f / (1.f + __expf(-(qf[f][nt][2] + bgs[c])));
                qf[f][nt][3] = 1.f / (1.f + __expf(-(qf[f][nt][3] + bgs[c + 1])));
            }
    }
    __syncthreads();                  // xs0/wt free

    // stage Wk|Wv; LN t0 -> xs0 (warps 0-7), LN t1 -> xs1 (warps 8-15)
    stageW2(wt, Wk, Wv, tid);
    if (wid < 8) ln128s(tmpl, base, R, xs0, gt, bt, wid, 8, lane);
    else if (T > 1) ln128s(tmpl + (long)R * CZ, base, R, xs1, gt, bt, wid - 8, 8, lane);

    float m8[8], l8[8];               // softmax state (K-warps, tig==0 authoritative)
    #pragma unroll
    for (int i = 0; i < 8; i++) { m8[i] = __int_as_float(0xff800000); l8[i] = 0.f; }
    float vAcc[2][4][4] = {};
    __syncthreads();

    // ---------------- template loop: 2 syncs per t, zero K/Q smem traffic ----------------
    #pragma unroll 1
    for (int t = 0; t < T; t++) {
        float kv[2][4][4] = {};
        gemm32(kv, (t & 1) ? xs1 : xs0, XST, wt, mt, nq, gid, tig, 16);

        if (isK) {                    // in-fragment scores + online softmax
            float sc[2][2][2];        // [f][rowhalf][headhalf]
            #pragma unroll
            for (int f = 0; f < 2; f++)
                #pragma unroll
                for (int hh = 0; hh < 2; hh++) {
                    const int nt0 = hh * 2;
                    #pragma unroll
                    for (int rh = 0; rh < 2; rh++) {
                        const int j = rh * 2;
                        float s = qf[f][nt0][j] * kv[f][nt0][j];
                        s = fmaf(qf[f][nt0][j + 1],     kv[f][nt0][j + 1],     s);
                        s = fmaf(qf[f][nt0 + 1][j],     kv[f][nt0 + 1][j],     s);
                        s = fmaf(qf[f][nt0 + 1][j + 1], kv[f][nt0 + 1][j + 1], s);
                        sc[f][rh][hh] = s;
                    }
                }
            #pragma unroll
            for (int f = 0; f < 2; f++)
                #pragma unroll
                for (int rh = 0; rh < 2; rh++)
                    #pragma unroll
                    for (int hh = 0; hh < 2; hh++) {
                        float v = sc[f][rh][hh];
                        v += __shfl_xor_sync(0xffffffffu, v, 1);
                        v += __shfl_xor_sync(0xffffffffu, v, 2);
                        sc[f][rh][hh] = v;
                    }
            if (tig == 0) {
                #pragma unroll
                for (int f = 0; f < 2; f++)
                    #pragma unroll
                    for (int rh = 0; rh < 2; rh++)
                        #pragma unroll
                        for (int hh = 0; hh < 2; hh++) {
                            const int i = f * 4 + rh * 2 + hh;
                            float sd = sc[f][rh][hh] * 0.25f;   // 1/sqrt(D=16)
                            float mn = fmaxf(m8[i], sd);
                            float rr = __expf(m8[i] - mn);
                            float ww = __expf(sd - mn);
                            l8[i] = l8[i] * rr + ww;
                            m8[i] = mn;
                            const int r = mt * 32 + f * 16 + rh * 8 + gid;
                            const int h = nq * 2 + hh;
                            rs[r * 4 + h] = rr;
                            ws[r * 4 + h] = ww;
                        }
            }
        }
        __syncthreads();              // S1: rs/ws ready; xs[t&1] fully read

        if (!isK) {                   // V online accumulate from fragments
            #pragma unroll
            for (int f = 0; f < 2; f++) {
                const int r0 = mt * 32 + f * 16 + gid, r1 = r0 + 8;
                #pragma unroll
                for (int nt = 0; nt < 4; nt++) {
                    const int h = ((nq - 2) * 32 + nt * 8) >> 4;
                    float rr0 = rs[r0 * 4 + h], ww0 = ws[r0 * 4 + h];
                    float rr1 = rs[r1 * 4 + h], ww1 = ws[r1 * 4 + h];
                    vAcc[f][nt][0] = fmaf(vAcc[f][nt][0], rr0, ww0 * kv[f][nt][0]);
                    vAcc[f][nt][1] = fmaf(vAcc[f][nt][1], rr0, ww0 * kv[f][nt][1]);
                    vAcc[f][nt][2] = fmaf(vAcc[f][nt][2], rr1, ww1 * kv[f][nt][2]);
                    vAcc[f][nt][3] = fmaf(vAcc[f][nt][3], rr1, ww1 * kv[f][nt][3]);
                }
            }
        }
        if (t + 2 < T)                // prefetch LN(t+2) into just-vacated buffer
            ln128s(tmpl + (long)(t + 2) * R * CZ, base, R,
                   (t & 1) ? xs1 : xs0, gt, bt, wid, 16, lane);
        if (t == T - 1) {             // last trip: stage Wo (wt free) + publish 1/l
            #pragma unroll 1
            for (int i = tid; i < 2048; i += NT) {
                const int k = i >> 5, ng = i & 31;
                float4 w = *(const float4*)(Wo + k * CZ + ng * 4);
                const int n = ng * 4;
                wt[(n + 0) * XST + k] = tf32r(w.x);
                wt[(n + 1) * XST + k] = tf32r(w.y);
                wt[(n + 2) * XST + k] = tf32r(w.z);
                wt[(n + 3) * XST + k] = tf32r(w.w);
            }
            if (isK && tig == 0) {
                #pragma unroll
                for (int f = 0; f < 2; f++)
                    #pragma unroll
                    for (int rh = 0; rh < 2; rh++)
                        #pragma unroll
                        for (int hh = 0; hh < 2; hh++) {
                            const int i = f * 4 + rh * 2 + hh;
                            const int r = mt * 32 + f * 16 + rh * 8 + gid;
                            ls[r * 4 + nq * 2 + hh] = 1.f / l8[i];
                        }
            }
        }
        __syncthreads();              // S2: xs(t+2)/Wo/ls ready; rs/ws consumed
    }

    // ---------------- Phase C: vals -> xs0, O GEMM ----------------
    if (!isK) {                       // vals = vAcc * G * linv  (G lives in qf)
        #pragma unroll
        for (int f = 0; f < 2; f++) {
            const int r0 = mt * 32 + f * 16 + gid, r1 = r0 + 8;
            #pragma unroll
            for (int nt = 0; nt < 4; nt++) {
                const int c = (nq - 2) * 32 + nt * 8 + tig * 2;
                const int h = ((nq - 2) * 32 + nt * 8) >> 4;
                float li0 = ls[r0 * 4 + h], li1 = ls[r1 * 4 + h];
                xs0[r0 * XST + c]     = tf32r(vAcc[f][nt][0] * qf[f][nt][0] * li0);
                xs0[r0 * XST + c + 1] = tf32r(vAcc[f][nt][1] * qf[f][nt][1] * li0);
                xs0[r1 * XST + c]     = tf32r(vAcc[f][nt][2] * qf[f][nt][2] * li1);
                xs0[r1 * XST + c + 1] = tf32r(vAcc[f][nt][3] * qf[f][nt][3] * li1);
            }
        }
    }
    __syncthreads();

    {
        float oc[2][4][4] = {};
        gemm32(oc, xs0, XST, wt, mt, nq, gid, tig, 8);
        #pragma unroll
        for (int f = 0; f < 2; f++) {
            const long r0 = base + mt * 32 + f * 16 + gid, r1 = r0 + 8;
            #pragma unroll
            for (int nt = 0; nt < 4; nt++) {
                const int c = nq * 32 + nt * 8 + tig * 2;
                if (r0 < R) {
                    float2 v = make_float2(oc[f][nt][0] + bos[c], oc[f][nt][1] + bos[c + 1]);
                    *(float2*)(out + r0 * (long)CZ + c) = v;
                }
                if (r1 < R) {
                    float2 v = make_float2(oc[f][nt][2] + bos[c], oc[f][nt][3] + bos[c + 1]);
                    *(float2*)(out + r1 * (long)CZ + c) = v;
                }
            }
        }
    }
}

extern "C" void kernel_launch(void* const* d_in, const int* in_sizes, int n_in,
                              void* d_out, int out_size)
{
    const float* tmpl = (const float*)d_in[0];
    const float* pair = (const float*)d_in[1];
    const float* lpg  = (const float*)d_in[2];
    const float* lpb  = (const float*)d_in[3];
    const float* ltg  = (const float*)d_in[4];
    const float* ltb  = (const float*)d_in[5];
    const float* Wq   = (const float*)d_in[6];
    const float* Wk   = (const float*)d_in[7];
    const float* Wv   = (const float*)d_in[8];
    const float* Wg   = (const float*)d_in[9];
    const float* bg   = (const float*)d_in[10];
    const float* Wo   = (const float*)d_in[11];
    const float* bo   = (const float*)d_in[12];
    float* out = (float*)d_out;

    const int R = in_sizes[1] / CZ;           // b*n*n pixels
    const int T = in_sizes[0] / in_sizes[1];  // templates

    const size_t smem = (size_t)(3 * P * XST + 3 * 512 + HD + CZ) * sizeof(float);
    cudaFuncSetAttribute(tpa_mma6, cudaFuncAttributeMaxDynamicSharedMemorySize, (int)smem);

    const int grid = (R + P - 1) / P;
    tpa_mma6<<<grid, NT, smem>>>(tmpl, pair, lpg, lpb, ltg, ltb,
                                 Wq, Wk, Wv, Wg, bg, Wo, bo, out, R, T);
}